// round 4
// baseline (speedup 1.0000x reference)
#include <cuda_runtime.h>
#include <math.h>
#include <stdint.h>

#define BB 2
#define TSEQ 2048
#define HDIM 1024
#define DD 64
#define MM 16
#define NTILE (TSEQ/64)   // 32 tiles of 64 rows

// ---------------- device scratch (no allocations allowed) ----------------
__device__ float g_q[(size_t)BB*MM*TSEQ*DD];
__device__ float g_k[(size_t)BB*MM*TSEQ*DD];
__device__ float g_v[(size_t)BB*MM*TSEQ*DD];
__device__ float g_entp[BB*MM*NTILE];
__device__ float g_nmask[BB*MM];
__device__ float g_oproj[(size_t)BB*DD*HDIM];
__device__ float g_comb[(size_t)BB*TSEQ*DD];
__device__ float g_sha[(size_t)BB*TSEQ*MM*DD];   // fallback if out buffer lacks sha region

// swizzled index into a 64x64 float tile: XOR the float4-chunk id with (row&15)
__device__ __forceinline__ int swz(int row, int col) {
    return row*64 + ((((col >> 2) ^ (row & 15)) << 2) | (col & 3));
}

// ============================================================================
// K1: QKV projection.  q/k/v[b,m,t,d] = sum_h hs[b,t,h] * w{q,k,v}[m,h,d]
// Block = one (b,m,t-tile): 64 rows x 64 cols (full D), K=1024 in BK=16 steps.
// ============================================================================
__global__ void __launch_bounds__(256) k_qkv(const float* __restrict__ hs,
                                             const float* __restrict__ wq,
                                             const float* __restrict__ wk,
                                             const float* __restrict__ wv)
{
    __shared__ float Ast[16*64];   // [k][t] transposed
    __shared__ float Wqs[16*64];   // [k][d]
    __shared__ float Wks[16*64];
    __shared__ float Wvs[16*64];

    const int bm = blockIdx.y;
    const int m  = bm & 15;
    const int b  = bm >> 4;
    const int ti = blockIdx.x;
    const int tid = threadIdx.x;
    const int tx = tid & 15, ty = tid >> 4;

    const float* A  = hs + ((size_t)b*TSEQ + (size_t)ti*64) * HDIM;
    const float* pq = wq + (size_t)m*HDIM*DD;
    const float* pk = wk + (size_t)m*HDIM*DD;
    const float* pv = wv + (size_t)m*HDIM*DD;

    const int lr = tid >> 2;          // 0..63 : A row
    const int lc = (tid & 3) << 2;    // 0,4,8,12 : A k-offset
    const int wr = tid >> 4;          // 0..15 : W k-row
    const int wc = (tid & 15) << 2;   // 0..60 : W d-offset

    float aq[16], ak[16], av[16];
#pragma unroll
    for (int i = 0; i < 16; i++) { aq[i] = 0.f; ak[i] = 0.f; av[i] = 0.f; }

    for (int kk = 0; kk < HDIM; kk += 16) {
        float4 a4 = *(const float4*)&A[(size_t)lr*HDIM + kk + lc];
        float4 q4 = *(const float4*)&pq[(size_t)(kk+wr)*DD + wc];
        float4 k4 = *(const float4*)&pk[(size_t)(kk+wr)*DD + wc];
        float4 v4 = *(const float4*)&pv[(size_t)(kk+wr)*DD + wc];
        __syncthreads();
        Ast[(lc+0)*64+lr] = a4.x; Ast[(lc+1)*64+lr] = a4.y;
        Ast[(lc+2)*64+lr] = a4.z; Ast[(lc+3)*64+lr] = a4.w;
        *(float4*)&Wqs[wr*64+wc] = q4;
        *(float4*)&Wks[wr*64+wc] = k4;
        *(float4*)&Wvs[wr*64+wc] = v4;
        __syncthreads();
#pragma unroll
        for (int k = 0; k < 16; k++) {
            float4 a  = *(float4*)&Ast[k*64 + 4*ty];
            float4 bq = *(float4*)&Wqs[k*64 + 4*tx];
            float4 bk = *(float4*)&Wks[k*64 + 4*tx];
            float4 bv = *(float4*)&Wvs[k*64 + 4*tx];
            float aa[4] = {a.x, a.y, a.z, a.w};
            float qb[4] = {bq.x, bq.y, bq.z, bq.w};
            float kb[4] = {bk.x, bk.y, bk.z, bk.w};
            float vb[4] = {bv.x, bv.y, bv.z, bv.w};
#pragma unroll
            for (int i = 0; i < 4; i++)
#pragma unroll
                for (int j = 0; j < 4; j++) {
                    aq[i*4+j] += aa[i]*qb[j];
                    ak[i*4+j] += aa[i]*kb[j];
                    av[i*4+j] += aa[i]*vb[j];
                }
        }
    }
    const size_t ob = ((size_t)bm*TSEQ + (size_t)ti*64) * DD;
#pragma unroll
    for (int i = 0; i < 4; i++) {
        size_t off = ob + (size_t)(4*ty+i)*64 + 4*tx;
        *(float4*)&g_q[off] = make_float4(aq[i*4], aq[i*4+1], aq[i*4+2], aq[i*4+3]);
        *(float4*)&g_k[off] = make_float4(ak[i*4], ak[i*4+1], ak[i*4+2], ak[i*4+3]);
        *(float4*)&g_v[off] = make_float4(av[i*4], av[i*4+1], av[i*4+2], av[i*4+3]);
    }
}

// ============================================================================
// K2: flash attention + streaming entropy, one block per (b,m,q-tile of 64).
//   entropy_t = log(Z) - SW/Z,  Z = sum e^{s-m},  SW = sum e^{s-m}(s-m)
// sha written as [B,T,M,D]; per-tile entropy partial -> g_entp (deterministic).
// ============================================================================
__global__ void __launch_bounds__(256) k_attn(float* __restrict__ osha)
{
    __shared__ float Qt[64*64];   // [d][t], prescaled by 1/sqrt(D)
    __shared__ float KP[64*64];   // swizzled: K as [d][j], then P as [j][t]
    __shared__ float Vs[64*64];   // [j][d]

    float* shaP = osha ? osha : g_sha;

    const int bm = blockIdx.y;
    const int m  = bm & 15;
    const int b  = bm >> 4;
    const int ti = blockIdx.x;
    const int tid = threadIdx.x;
    const int tx = tid & 15, ty = tid >> 4;

    const size_t qbase  = ((size_t)bm*TSEQ + (size_t)ti*64) * DD;
    const size_t kvbase = (size_t)bm*TSEQ*DD;

    // load Q transposed, prescaled (one-time; store conflicts are amortized)
#pragma unroll
    for (int it = 0; it < 4; it++) {
        int cid = it*256 + tid;
        int r  = cid >> 4;
        int c0 = (cid & 15) << 2;
        float4 v = *(const float4*)&g_q[qbase + (size_t)r*64 + c0];
        Qt[(c0+0)*64 + r] = v.x*0.125f;
        Qt[(c0+1)*64 + r] = v.y*0.125f;
        Qt[(c0+2)*64 + r] = v.z*0.125f;
        Qt[(c0+3)*64 + r] = v.w*0.125f;
    }

    float o[16];
#pragma unroll
    for (int i = 0; i < 16; i++) o[i] = 0.f;
    float mr[4], Zr[4], SWr[4];
#pragma unroll
    for (int i = 0; i < 4; i++) { mr[i] = -1e30f; Zr[i] = 0.f; SWr[i] = 0.f; }

    for (int jt = 0; jt < NTILE; jt++) {
        __syncthreads();  // previous PV GEMM done before overwriting KP/Vs
#pragma unroll
        for (int it = 0; it < 4; it++) {
            int cid = it*256 + tid;
            int j  = cid >> 4;
            int d0 = (cid & 15) << 2;
            size_t goff = kvbase + ((size_t)jt*64 + j)*64 + d0;
            float4 kv = *(const float4*)&g_k[goff];
            KP[swz(d0+0, j)] = kv.x;
            KP[swz(d0+1, j)] = kv.y;
            KP[swz(d0+2, j)] = kv.z;
            KP[swz(d0+3, j)] = kv.w;
            float4 vv = *(const float4*)&g_v[goff];
            *(float4*)&Vs[j*64 + d0] = vv;
        }
        __syncthreads();

        // S = (Q/sqrt(D)) K^T : s[i*4+jj] = S[4ty+i][4tx+jj]
        float s[16];
#pragma unroll
        for (int i = 0; i < 16; i++) s[i] = 0.f;
#pragma unroll 8
        for (int k = 0; k < 64; k++) {
            float4 a  = *(float4*)&Qt[k*64 + 4*ty];
            float4 bb = *(float4*)&KP[k*64 + ((tx ^ (k & 15)) << 2)];
            float aa[4] = {a.x, a.y, a.z, a.w};
            float bv[4] = {bb.x, bb.y, bb.z, bb.w};
#pragma unroll
            for (int i = 0; i < 4; i++)
#pragma unroll
                for (int jj = 0; jj < 4; jj++) s[i*4+jj] += aa[i]*bv[jj];
        }
        __syncthreads();  // all threads done reading K before P overwrites KP

        // online softmax + entropy update per row
#pragma unroll
        for (int i = 0; i < 4; i++) {
            float mx = fmaxf(fmaxf(s[i*4], s[i*4+1]), fmaxf(s[i*4+2], s[i*4+3]));
#pragma unroll
            for (int off = 8; off >= 1; off >>= 1)
                mx = fmaxf(mx, __shfl_xor_sync(0xffffffffu, mx, off, 16));
            float mnew  = fmaxf(mr[i], mx);
            float dlt   = mr[i] - mnew;          // finite: mr init -1e30
            float alpha = __expf(dlt);
            float ps = 0.f, pws = 0.f;
#pragma unroll
            for (int jj = 0; jj < 4; jj++) {
                float x = s[i*4+jj] - mnew;
                float p = __expf(x);
                ps  += p;
                pws += p * x;
                s[i*4+jj] = p;
            }
#pragma unroll
            for (int off = 8; off >= 1; off >>= 1) {
                ps  += __shfl_xor_sync(0xffffffffu, ps,  off, 16);
                pws += __shfl_xor_sync(0xffffffffu, pws, off, 16);
            }
            SWr[i] = alpha*(SWr[i] + dlt*Zr[i]) + pws;
            Zr[i]  = alpha*Zr[i] + ps;
            mr[i]  = mnew;
            o[i*4+0] *= alpha; o[i*4+1] *= alpha;
            o[i*4+2] *= alpha; o[i*4+3] *= alpha;
        }

        // store P transposed (swizzled) into KP: P[t][j] -> KP[j][t]
#pragma unroll
        for (int jj = 0; jj < 4; jj++) {
            int col = 4*tx + jj;
            *(float4*)&KP[col*64 + ((ty ^ (col & 15)) << 2)] =
                make_float4(s[jj], s[4+jj], s[8+jj], s[12+jj]);
        }
        __syncthreads();

        // O += P V
#pragma unroll 8
        for (int j = 0; j < 64; j++) {
            float4 a  = *(float4*)&KP[j*64 + ((ty ^ (j & 15)) << 2)];
            float4 bb = *(float4*)&Vs[j*64 + 4*tx];
            float aa[4] = {a.x, a.y, a.z, a.w};
            float bv[4] = {bb.x, bb.y, bb.z, bb.w};
#pragma unroll
            for (int i = 0; i < 4; i++)
#pragma unroll
                for (int jj = 0; jj < 4; jj++) o[i*4+jj] += aa[i]*bv[jj];
        }
    }

    __syncthreads();
    // epilogue: normalize, store sha [B,T,M,D], entropy partial
#pragma unroll
    for (int i = 0; i < 4; i++) {
        float inv = 1.f / Zr[i];
        int t = ti*64 + 4*ty + i;
        size_t off = (((size_t)b*TSEQ + t)*MM + m)*DD + 4*tx;
        *(float4*)&shaP[off] = make_float4(o[i*4]*inv, o[i*4+1]*inv,
                                           o[i*4+2]*inv, o[i*4+3]*inv);
        if (tx == 0) KP[4*ty + i] = logf(Zr[i]) - SWr[i]*inv;
    }
    __syncthreads();
    if (tid == 0) {
        float sum = 0.f;
#pragma unroll
        for (int r = 0; r < 64; r++) sum += KP[r];
        g_entp[bm*NTILE + ti] = sum;
    }
}

// ============================================================================
// K3: gating (1 warp). affinity -> standardize (ddof=1) -> logits/mask ->
// fallback top-2 -> normalized mask; writes small outputs + g_nmask.
// ============================================================================
__global__ void k_gate(const float* __restrict__ gates,
                       float* __restrict__ out_logits,
                       float* __restrict__ out_mask,
                       float* __restrict__ out_cnt)
{
    __shared__ float zs[32];
    __shared__ int   inac[2];
    const int tid = threadIdx.x;      // 0..31
    const int b = tid >> 4, m = tid & 15;

    float es = 0.f;
#pragma unroll
    for (int i = 0; i < NTILE; i++) es += g_entp[(b*MM + m)*NTILE + i];
    float aff = -(es / (float)TSEQ);

    float mu = aff;
#pragma unroll
    for (int off = 8; off >= 1; off >>= 1) mu += __shfl_xor_sync(0xffffffffu, mu, off, 16);
    mu *= (1.f/16.f);
    float dv = (aff - mu) * (aff - mu);
#pragma unroll
    for (int off = 8; off >= 1; off >>= 1) dv += __shfl_xor_sync(0xffffffffu, dv, off, 16);
    float sd = sqrtf(dv * (1.f/15.f));            // ddof=1
    float z  = (aff - mu) / (sd + 1e-9f);

    float sig   = 1.f / (1.f + expf(-gates[m]));
    float logit = z - sig;
    float hard  = (logit > 0.f) ? 1.f : 0.f;

    float nh = hard;
#pragma unroll
    for (int off = 8; off >= 1; off >>= 1) nh += __shfl_xor_sync(0xffffffffu, nh, off, 16);

    zs[tid] = z;
    __syncwarp();
    int rank = 0;
#pragma unroll
    for (int j = 0; j < 16; j++) {
        float zj = zs[b*16 + j];
        if (zj > z || (zj == z && j < m)) rank++;
    }
    int inactive = (nh == 0.f) ? 1 : 0;
    float mask = hard;
    if (inactive && rank < 2) mask = 1.f;   // fallback top-K_FALLBACK=2

    float na = mask;
#pragma unroll
    for (int off = 8; off >= 1; off >>= 1) na += __shfl_xor_sync(0xffffffffu, na, off, 16);
    float nm = mask / fmaxf(na, 1.f);

    g_nmask[tid] = nm;
    if (out_logits) out_logits[tid] = logit;
    if (out_mask)   out_mask[tid]   = mask;
    if (m == 0) inac[b] = inactive;
    __syncwarp();
    if (tid == 0 && out_cnt) out_cnt[0] = (float)(inac[0] + inac[1]);
}

// K4a: dynamic_o_proj[b,d,h] = sum_m o_weights[m,d,h] * nmask[b,m]
__global__ void k_oproj(const float* __restrict__ ow)
{
    const int b = blockIdx.y;
    const int i = blockIdx.x*256 + threadIdx.x;  // 0 .. D*H-1
    float s = 0.f;
#pragma unroll
    for (int m = 0; m < MM; m++)
        s += ow[(size_t)m*DD*HDIM + i] * g_nmask[b*MM + m];
    g_oproj[(size_t)b*DD*HDIM + i] = s;
}

// K4b: combined[b,t,d] = sum_m sha[b,t,m,d] * nmask[b,m]
__global__ void k_comb(const float* __restrict__ osha)
{
    const float* shaP = osha ? osha : g_sha;
    const int idx = blockIdx.x*256 + threadIdx.x;  // 0 .. B*T*D-1
    const int d  = idx & 63;
    const int bt = idx >> 6;
    const int b  = bt >> 11;                       // T = 2048
    float s = 0.f;
#pragma unroll
    for (int m = 0; m < MM; m++)
        s += shaP[((size_t)bt*MM + m)*DD + d] * g_nmask[b*MM + m];
    g_comb[idx] = s;
}

// K5: final[b,t,h] = sum_d combined[b,t,d] * oproj[b,d,h]   (K=64, one pass)
__global__ void __launch_bounds__(256) k_final(float* __restrict__ outp)
{
    __shared__ float Ct[64*64];  // [d][t]
    __shared__ float Os[64*64];  // [d][h]
    const int ti = blockIdx.x, hb = blockIdx.y, b = blockIdx.z;
    const int tid = threadIdx.x;
    const int tx = tid & 15, ty = tid >> 4;

#pragma unroll
    for (int it = 0; it < 4; it++) {
        int cid = it*256 + tid;
        int r  = cid >> 4;
        int c0 = (cid & 15) << 2;
        float4 cv = *(const float4*)&g_comb[((size_t)b*TSEQ + (size_t)ti*64 + r)*64 + c0];
        Ct[(c0+0)*64+r] = cv.x; Ct[(c0+1)*64+r] = cv.y;
        Ct[(c0+2)*64+r] = cv.z; Ct[(c0+3)*64+r] = cv.w;
        float4 pv4 = *(const float4*)&g_oproj[(size_t)b*DD*HDIM + (size_t)r*HDIM + hb*64 + c0];
        *(float4*)&Os[r*64 + c0] = pv4;
    }
    __syncthreads();

    float acc[16];
#pragma unroll
    for (int i = 0; i < 16; i++) acc[i] = 0.f;
#pragma unroll 8
    for (int k = 0; k < 64; k++) {
        float4 a  = *(float4*)&Ct[k*64 + 4*ty];
        float4 bb = *(float4*)&Os[k*64 + 4*tx];
        float aa[4] = {a.x, a.y, a.z, a.w};
        float bv[4] = {bb.x, bb.y, bb.z, bb.w};
#pragma unroll
        for (int i = 0; i < 4; i++)
#pragma unroll
            for (int jj = 0; jj < 4; jj++) acc[i*4+jj] += aa[i]*bv[jj];
    }
#pragma unroll
    for (int i = 0; i < 4; i++) {
        size_t off = ((size_t)b*TSEQ + (size_t)ti*64 + 4*ty + i)*HDIM + hb*64 + 4*tx;
        *(float4*)&outp[off] = make_float4(acc[i*4], acc[i*4+1], acc[i*4+2], acc[i*4+3]);
    }
}

// ============================================================================
extern "C" void kernel_launch(void* const* d_in, const int* in_sizes, int n_in,
                              void* d_out, int out_size)
{
    const float* hs    = (const float*)d_in[0];
    const float* wq    = (const float*)d_in[1];
    const float* wk    = (const float*)d_in[2];
    const float* wv    = (const float*)d_in[3];
    const float* ow    = (const float*)d_in[4];
    const float* gates = (const float*)d_in[5];
    float* out = (float*)d_out;

    const long long SZ_FINAL = (long long)BB*TSEQ*HDIM;     // 4194304
    const long long SZ_SHA   = (long long)BB*TSEQ*MM*DD;    // 4194304
    const bool full = (long long)out_size >= SZ_FINAL + SZ_SHA + 2*BB*MM + 1;

    float* p_sha    = full ? out + SZ_FINAL : nullptr;
    float* p_logits = full ? out + SZ_FINAL + SZ_SHA : nullptr;
    float* p_mask   = full ? out + SZ_FINAL + SZ_SHA + BB*MM : nullptr;
    float* p_cnt    = full ? out + SZ_FINAL + SZ_SHA + 2*BB*MM : nullptr;

    k_qkv  <<<dim3(NTILE, BB*MM), 256>>>(hs, wq, wk, wv);
    k_attn <<<dim3(NTILE, BB*MM), 256>>>(p_sha);
    k_gate <<<1, 32>>>(gates, p_logits, p_mask, p_cnt);
    k_oproj<<<dim3(DD*HDIM/256, BB), 256>>>(ow);
    k_comb <<<(BB*TSEQ*DD)/256, 256>>>(p_sha);
    k_final<<<dim3(NTILE, HDIM/64, BB), 256>>>(out);
}

// round 6
// speedup vs baseline: 1.0274x; 1.0274x over previous
#include <cuda_runtime.h>
#include <math.h>
#include <stdint.h>

#define BB 2
#define TSEQ 2048
#define HDIM 1024
#define DD 64
#define MM 16
#define NTILE (TSEQ/64)   // 32 tiles of 64 rows

typedef unsigned long long ull;

// ---------------- f32x2 packed-FMA helpers (Blackwell FFMA2) ----------------
__device__ __forceinline__ ull pk2(float lo, float hi) {
    ull r; asm("mov.b64 %0, {%1, %2};" : "=l"(r) : "f"(lo), "f"(hi)); return r;
}
__device__ __forceinline__ void upk2(ull v, float& lo, float& hi) {
    asm("mov.b64 {%0, %1}, %2;" : "=f"(lo), "=f"(hi) : "l"(v));
}
__device__ __forceinline__ void fma2(ull& d, ull a, ull b) {
    asm("fma.rn.f32x2 %0, %1, %2, %0;" : "+l"(d) : "l"(a), "l"(b));
}
__device__ __forceinline__ void mul2(ull& d, ull a) {
    asm("mul.rn.f32x2 %0, %0, %1;" : "+l"(d) : "l"(a));
}

// ---------------- device scratch (no allocations allowed) ----------------
__device__ float g_q[(size_t)BB*MM*TSEQ*DD];
__device__ float g_k[(size_t)BB*MM*TSEQ*DD];
__device__ float g_v[(size_t)BB*MM*TSEQ*DD];
__device__ float g_entp[BB*MM*NTILE];
__device__ float g_nmask[BB*MM];
__device__ float g_oproj[(size_t)BB*DD*HDIM];
__device__ float g_comb[(size_t)BB*TSEQ*DD];
__device__ float g_sha[(size_t)BB*TSEQ*MM*DD];   // fallback if out buffer lacks sha region

// swizzled index into a 64x64 float tile: XOR the float4-chunk id with (row&15)
__device__ __forceinline__ int swz(int row, int col) {
    return row*64 + ((((col >> 2) ^ (row & 15)) << 2) | (col & 3));
}

// ============================================================================
// K1: QKV projection.  q/k/v[b,m,t,d] = sum_h hs[b,t,h] * w{q,k,v}[m,h,d]
// Block = one (b,m,t-tile): 64 rows x 64 cols (full D), K=1024 in BK=16 steps.
// Inner product in f32x2: acc pairs along d (j), a broadcast-packed.
// ============================================================================
__global__ void __launch_bounds__(256) k_qkv(const float* __restrict__ hs,
                                             const float* __restrict__ wq,
                                             const float* __restrict__ wk,
                                             const float* __restrict__ wv)
{
    __shared__ float Ast[16*64];   // [k][t] transposed
    __shared__ float Wqs[16*64];   // [k][d]
    __shared__ float Wks[16*64];
    __shared__ float Wvs[16*64];

    const int bm = blockIdx.y;
    const int m  = bm & 15;
    const int ti = blockIdx.x;
    const int tid = threadIdx.x;
    const int tx = tid & 15, ty = tid >> 4;
    const int b  = bm >> 4;

    const float* A  = hs + ((size_t)b*TSEQ + (size_t)ti*64) * HDIM;
    const float* pq = wq + (size_t)m*HDIM*DD;
    const float* pk = wk + (size_t)m*HDIM*DD;
    const float* pv = wv + (size_t)m*HDIM*DD;

    const int lr = tid >> 2;          // 0..63 : A row
    const int lc = (tid & 3) << 2;    // 0,4,8,12 : A k-offset
    const int wr = tid >> 4;          // 0..15 : W k-row
    const int wc = (tid & 15) << 2;   // 0..60 : W d-offset

    ull aq[8], ak[8], av[8];          // packed: [i][jpair], j pairs (0,1),(2,3)
#pragma unroll
    for (int i = 0; i < 8; i++) { aq[i] = 0ull; ak[i] = 0ull; av[i] = 0ull; }

    for (int kk = 0; kk < HDIM; kk += 16) {
        float4 a4 = *(const float4*)&A[(size_t)lr*HDIM + kk + lc];
        float4 q4 = *(const float4*)&pq[(size_t)(kk+wr)*DD + wc];
        float4 k4 = *(const float4*)&pk[(size_t)(kk+wr)*DD + wc];
        float4 v4 = *(const float4*)&pv[(size_t)(kk+wr)*DD + wc];
        __syncthreads();
        Ast[(lc+0)*64+lr] = a4.x; Ast[(lc+1)*64+lr] = a4.y;
        Ast[(lc+2)*64+lr] = a4.z; Ast[(lc+3)*64+lr] = a4.w;
        *(float4*)&Wqs[wr*64+wc] = q4;
        *(float4*)&Wks[wr*64+wc] = k4;
        *(float4*)&Wvs[wr*64+wc] = v4;
        __syncthreads();
#pragma unroll
        for (int k = 0; k < 16; k++) {
            float4 a = *(float4*)&Ast[k*64 + 4*ty];
            ulonglong2 q2 = *(ulonglong2*)&Wqs[k*64 + 4*tx];
            ulonglong2 k2 = *(ulonglong2*)&Wks[k*64 + 4*tx];
            ulonglong2 v2 = *(ulonglong2*)&Wvs[k*64 + 4*tx];
            ull ab[4] = { pk2(a.x,a.x), pk2(a.y,a.y), pk2(a.z,a.z), pk2(a.w,a.w) };
#pragma unroll
            for (int i = 0; i < 4; i++) {
                fma2(aq[i*2+0], ab[i], q2.x); fma2(aq[i*2+1], ab[i], q2.y);
                fma2(ak[i*2+0], ab[i], k2.x); fma2(ak[i*2+1], ab[i], k2.y);
                fma2(av[i*2+0], ab[i], v2.x); fma2(av[i*2+1], ab[i], v2.y);
            }
        }
    }
    const size_t ob = ((size_t)bm*TSEQ + (size_t)ti*64) * DD;
#pragma unroll
    for (int i = 0; i < 4; i++) {
        size_t off = ob + (size_t)(4*ty+i)*64 + 4*tx;
        ulonglong2 uq; uq.x = aq[i*2]; uq.y = aq[i*2+1];
        ulonglong2 uk; uk.x = ak[i*2]; uk.y = ak[i*2+1];
        ulonglong2 uv; uv.x = av[i*2]; uv.y = av[i*2+1];
        *(float4*)&g_q[off] = *(float4*)&uq;
        *(float4*)&g_k[off] = *(float4*)&uk;
        *(float4*)&g_v[off] = *(float4*)&uv;
    }
}

// ============================================================================
// K2: flash attention + streaming entropy, one block per (b,m,q-tile of 64).
//   entropy_t = log(Z) - SW/Z,  Z = sum e^{s-m},  SW = sum e^{s-m}(s-m)
// S-GEMM: acc pairs along j (K columns pair-loaded from swizzled smem).
// PV-GEMM: acc pairs along i (P^T rows pair-loaded), V broadcast-packed.
// ============================================================================
__global__ void __launch_bounds__(256) k_attn(float* __restrict__ osha)
{
    __shared__ float Qt[64*64];   // [d][t], prescaled by 1/sqrt(D)
    __shared__ float KP[64*64];   // swizzled: K as [d][j], then P as [j][t]
    __shared__ float Vs[64*64];   // [j][d]

    float* shaP = osha ? osha : g_sha;

    const int bm = blockIdx.y;
    const int m  = bm & 15;
    const int b  = bm >> 4;
    const int ti = blockIdx.x;
    const int tid = threadIdx.x;
    const int tx = tid & 15, ty = tid >> 4;

    const size_t qbase  = ((size_t)bm*TSEQ + (size_t)ti*64) * DD;
    const size_t kvbase = (size_t)bm*TSEQ*DD;

#pragma unroll
    for (int it = 0; it < 4; it++) {
        int cid = it*256 + tid;
        int r  = cid >> 4;
        int c0 = (cid & 15) << 2;
        float4 v = *(const float4*)&g_q[qbase + (size_t)r*64 + c0];
        Qt[(c0+0)*64 + r] = v.x*0.125f;
        Qt[(c0+1)*64 + r] = v.y*0.125f;
        Qt[(c0+2)*64 + r] = v.z*0.125f;
        Qt[(c0+3)*64 + r] = v.w*0.125f;
    }

    ull o2[8];                    // packed over i: [ipair][j], ipair0=(rows0,1)
#pragma unroll
    for (int i = 0; i < 8; i++) o2[i] = 0ull;
    float mr[4], Zr[4], SWr[4];
#pragma unroll
    for (int i = 0; i < 4; i++) { mr[i] = -1e30f; Zr[i] = 0.f; SWr[i] = 0.f; }

    for (int jt = 0; jt < NTILE; jt++) {
        __syncthreads();  // previous PV GEMM done before overwriting KP/Vs
#pragma unroll
        for (int it = 0; it < 4; it++) {
            int cid = it*256 + tid;
            int j  = cid >> 4;
            int d0 = (cid & 15) << 2;
            size_t goff = kvbase + ((size_t)jt*64 + j)*64 + d0;
            float4 kv = *(const float4*)&g_k[goff];
            KP[swz(d0+0, j)] = kv.x;
            KP[swz(d0+1, j)] = kv.y;
            KP[swz(d0+2, j)] = kv.z;
            KP[swz(d0+3, j)] = kv.w;
            float4 vv = *(const float4*)&g_v[goff];
            *(float4*)&Vs[j*64 + d0] = vv;
        }
        __syncthreads();

        // S = (Q/sqrt(D)) K^T  — packed over j
        ull s2[8];
#pragma unroll
        for (int i = 0; i < 8; i++) s2[i] = 0ull;
#pragma unroll 8
        for (int k = 0; k < 64; k++) {
            float4 a = *(float4*)&Qt[k*64 + 4*ty];
            ulonglong2 b2 = *(ulonglong2*)&KP[k*64 + ((tx ^ (k & 15)) << 2)];
            ull ab[4] = { pk2(a.x,a.x), pk2(a.y,a.y), pk2(a.z,a.z), pk2(a.w,a.w) };
#pragma unroll
            for (int i = 0; i < 4; i++) {
                fma2(s2[i*2+0], ab[i], b2.x);
                fma2(s2[i*2+1], ab[i], b2.y);
            }
        }
        __syncthreads();  // all threads done reading K before P overwrites KP

        // unpack scores to scalars for softmax
        float s[16];
#pragma unroll
        for (int i = 0; i < 4; i++) {
            upk2(s2[i*2+0], s[i*4+0], s[i*4+1]);
            upk2(s2[i*2+1], s[i*4+2], s[i*4+3]);
        }

        // online softmax + entropy update per row
        float alph[4];
#pragma unroll
        for (int i = 0; i < 4; i++) {
            float mx = fmaxf(fmaxf(s[i*4], s[i*4+1]), fmaxf(s[i*4+2], s[i*4+3]));
#pragma unroll
            for (int off = 8; off >= 1; off >>= 1)
                mx = fmaxf(mx, __shfl_xor_sync(0xffffffffu, mx, off, 16));
            float mnew  = fmaxf(mr[i], mx);
            float dlt   = mr[i] - mnew;          // finite: mr init -1e30
            float alpha = __expf(dlt);
            float ps = 0.f, pws = 0.f;
#pragma unroll
            for (int jj = 0; jj < 4; jj++) {
                float x = s[i*4+jj] - mnew;
                float p = __expf(x);
                ps  += p;
                pws += p * x;
                s[i*4+jj] = p;
            }
#pragma unroll
            for (int off = 8; off >= 1; off >>= 1) {
                ps  += __shfl_xor_sync(0xffffffffu, ps,  off, 16);
                pws += __shfl_xor_sync(0xffffffffu, pws, off, 16);
            }
            SWr[i] = alpha*(SWr[i] + dlt*Zr[i]) + pws;
            Zr[i]  = alpha*Zr[i] + ps;
            mr[i]  = mnew;
            alph[i] = alpha;
        }
        // rescale packed O accumulators (per-row alpha packed per i-pair)
        {
            ull a01 = pk2(alph[0], alph[1]);
            ull a23 = pk2(alph[2], alph[3]);
#pragma unroll
            for (int j = 0; j < 4; j++) { mul2(o2[j], a01); mul2(o2[4+j], a23); }
        }

        // store P transposed (swizzled) into KP: P[t][j] -> KP[j][t]
#pragma unroll
        for (int jj = 0; jj < 4; jj++) {
            int col = 4*tx + jj;
            *(float4*)&KP[col*64 + ((ty ^ (col & 15)) << 2)] =
                make_float4(s[jj], s[4+jj], s[8+jj], s[12+jj]);
        }
        __syncthreads();

        // O += P V  — packed over i (P^T rows pair-loaded)
#pragma unroll 8
        for (int j = 0; j < 64; j++) {
            ulonglong2 a2 = *(ulonglong2*)&KP[j*64 + ((ty ^ (j & 15)) << 2)];
            float4 bb = *(float4*)&Vs[j*64 + 4*tx];
            ull bp[4] = { pk2(bb.x,bb.x), pk2(bb.y,bb.y), pk2(bb.z,bb.z), pk2(bb.w,bb.w) };
#pragma unroll
            for (int jj = 0; jj < 4; jj++) {
                fma2(o2[jj],   a2.x, bp[jj]);
                fma2(o2[4+jj], a2.y, bp[jj]);
            }
        }
    }

    __syncthreads();
    // unpack O: ov[i][jj]
    float ov[16];
#pragma unroll
    for (int jj = 0; jj < 4; jj++) {
        upk2(o2[jj],   ov[0*4+jj], ov[1*4+jj]);
        upk2(o2[4+jj], ov[2*4+jj], ov[3*4+jj]);
    }
    // epilogue: normalize, store sha [B,T,M,D], entropy partial
#pragma unroll
    for (int i = 0; i < 4; i++) {
        float inv = 1.f / Zr[i];
        int t = ti*64 + 4*ty + i;
        size_t off = (((size_t)b*TSEQ + t)*MM + m)*DD + 4*tx;
        *(float4*)&shaP[off] = make_float4(ov[i*4]*inv, ov[i*4+1]*inv,
                                           ov[i*4+2]*inv, ov[i*4+3]*inv);
        if (tx == 0) KP[4*ty + i] = logf(Zr[i]) - SWr[i]*inv;
    }
    __syncthreads();
    if (tid == 0) {
        float sum = 0.f;
#pragma unroll
        for (int r = 0; r < 64; r++) sum += KP[r];
        g_entp[bm*NTILE + ti] = sum;
    }
}

// ============================================================================
// K3: gating (1 warp). affinity -> standardize (ddof=1) -> logits/mask ->
// fallback top-2 -> normalized mask; writes small outputs + g_nmask.
// ============================================================================
__global__ void k_gate(const float* __restrict__ gates,
                       float* __restrict__ out_logits,
                       float* __restrict__ out_mask,
                       float* __restrict__ out_cnt)
{
    __shared__ float zs[32];
    __shared__ int   inac[2];
    const int tid = threadIdx.x;      // 0..31
    const int b = tid >> 4, m = tid & 15;

    float es = 0.f;
#pragma unroll
    for (int i = 0; i < NTILE; i++) es += g_entp[(b*MM + m)*NTILE + i];
    float aff = -(es / (float)TSEQ);

    float mu = aff;
#pragma unroll
    for (int off = 8; off >= 1; off >>= 1) mu += __shfl_xor_sync(0xffffffffu, mu, off, 16);
    mu *= (1.f/16.f);
    float dv = (aff - mu) * (aff - mu);
#pragma unroll
    for (int off = 8; off >= 1; off >>= 1) dv += __shfl_xor_sync(0xffffffffu, dv, off, 16);
    float sd = sqrtf(dv * (1.f/15.f));            // ddof=1
    float z  = (aff - mu) / (sd + 1e-9f);

    float sig   = 1.f / (1.f + expf(-gates[m]));
    float logit = z - sig;
    float hard  = (logit > 0.f) ? 1.f : 0.f;

    float nh = hard;
#pragma unroll
    for (int off = 8; off >= 1; off >>= 1) nh += __shfl_xor_sync(0xffffffffu, nh, off, 16);

    zs[tid] = z;
    __syncwarp();
    int rank = 0;
#pragma unroll
    for (int j = 0; j < 16; j++) {
        float zj = zs[b*16 + j];
        if (zj > z || (zj == z && j < m)) rank++;
    }
    int inactive = (nh == 0.f) ? 1 : 0;
    float mask = hard;
    if (inactive && rank < 2) mask = 1.f;   // fallback top-K_FALLBACK=2

    float na = mask;
#pragma unroll
    for (int off = 8; off >= 1; off >>= 1) na += __shfl_xor_sync(0xffffffffu, na, off, 16);
    float nm = mask / fmaxf(na, 1.f);

    g_nmask[tid] = nm;
    if (out_logits) out_logits[tid] = logit;
    if (out_mask)   out_mask[tid]   = mask;
    if (m == 0) inac[b] = inactive;
    __syncwarp();
    if (tid == 0 && out_cnt) out_cnt[0] = (float)(inac[0] + inac[1]);
}

// K4a: dynamic_o_proj[b,d,h] = sum_m o_weights[m,d,h] * nmask[b,m]
__global__ void k_oproj(const float* __restrict__ ow)
{
    const int b = blockIdx.y;
    const int i = blockIdx.x*256 + threadIdx.x;  // 0 .. D*H-1
    float s = 0.f;
#pragma unroll
    for (int m = 0; m < MM; m++)
        s += ow[(size_t)m*DD*HDIM + i] * g_nmask[b*MM + m];
    g_oproj[(size_t)b*DD*HDIM + i] = s;
}

// K4b: combined[b,t,d] = sum_m sha[b,t,m,d] * nmask[b,m]
__global__ void k_comb(const float* __restrict__ osha)
{
    const float* shaP = osha ? osha : g_sha;
    const int idx = blockIdx.x*256 + threadIdx.x;  // 0 .. B*T*D-1
    const int d  = idx & 63;
    const int bt = idx >> 6;
    const int b  = bt >> 11;                       // T = 2048
    float s = 0.f;
#pragma unroll
    for (int m = 0; m < MM; m++)
        s += shaP[((size_t)bt*MM + m)*DD + d] * g_nmask[b*MM + m];
    g_comb[idx] = s;
}

// K5: final[b,t,h] = sum_d combined[b,t,d] * oproj[b,d,h]   (K=64, one pass)
__global__ void __launch_bounds__(256) k_final(float* __restrict__ outp)
{
    __shared__ float Ct[64*64];  // [d][t]
    __shared__ float Os[64*64];  // [d][h]
    const int ti = blockIdx.x, hb = blockIdx.y, b = blockIdx.z;
    const int tid = threadIdx.x;
    const int tx = tid & 15, ty = tid >> 4;

#pragma unroll
    for (int it = 0; it < 4; it++) {
        int cid = it*256 + tid;
        int r  = cid >> 4;
        int c0 = (cid & 15) << 2;
        float4 cv = *(const float4*)&g_comb[((size_t)b*TSEQ + (size_t)ti*64 + r)*64 + c0];
        Ct[(c0+0)*64+r] = cv.x; Ct[(c0+1)*64+r] = cv.y;
        Ct[(c0+2)*64+r] = cv.z; Ct[(c0+3)*64+r] = cv.w;
        float4 pv4 = *(const float4*)&g_oproj[(size_t)b*DD*HDIM + (size_t)r*HDIM + hb*64 + c0];
        *(float4*)&Os[r*64 + c0] = pv4;
    }
    __syncthreads();

    ull acc[8];
#pragma unroll
    for (int i = 0; i < 8; i++) acc[i] = 0ull;
#pragma unroll 8
    for (int k = 0; k < 64; k++) {
        float4 a = *(float4*)&Ct[k*64 + 4*ty];
        ulonglong2 b2 = *(ulonglong2*)&Os[k*64 + 4*tx];
        ull ab[4] = { pk2(a.x,a.x), pk2(a.y,a.y), pk2(a.z,a.z), pk2(a.w,a.w) };
#pragma unroll
        for (int i = 0; i < 4; i++) {
            fma2(acc[i*2+0], ab[i], b2.x);
            fma2(acc[i*2+1], ab[i], b2.y);
        }
    }
#pragma unroll
    for (int i = 0; i < 4; i++) {
        size_t off = ((size_t)b*TSEQ + (size_t)ti*64 + 4*ty + i)*HDIM + hb*64 + 4*tx;
        ulonglong2 u; u.x = acc[i*2]; u.y = acc[i*2+1];
        *(float4*)&outp[off] = *(float4*)&u;
    }
}

// ============================================================================
extern "C" void kernel_launch(void* const* d_in, const int* in_sizes, int n_in,
                              void* d_out, int out_size)
{
    const float* hs    = (const float*)d_in[0];
    const float* wq    = (const float*)d_in[1];
    const float* wk    = (const float*)d_in[2];
    const float* wv    = (const float*)d_in[3];
    const float* ow    = (const float*)d_in[4];
    const float* gates = (const float*)d_in[5];
    float* out = (float*)d_out;

    const long long SZ_FINAL = (long long)BB*TSEQ*HDIM;     // 4194304
    const long long SZ_SHA   = (long long)BB*TSEQ*MM*DD;    // 4194304
    const bool full = (long long)out_size >= SZ_FINAL + SZ_SHA + 2*BB*MM + 1;

    float* p_sha    = full ? out + SZ_FINAL : nullptr;
    float* p_logits = full ? out + SZ_FINAL + SZ_SHA : nullptr;
    float* p_mask   = full ? out + SZ_FINAL + SZ_SHA + BB*MM : nullptr;
    float* p_cnt    = full ? out + SZ_FINAL + SZ_SHA + 2*BB*MM : nullptr;

    k_qkv  <<<dim3(NTILE, BB*MM), 256>>>(hs, wq, wk, wv);
    k_attn <<<dim3(NTILE, BB*MM), 256>>>(p_sha);
    k_gate <<<1, 32>>>(gates, p_logits, p_mask, p_cnt);
    k_oproj<<<dim3(DD*HDIM/256, BB), 256>>>(ow);
    k_comb <<<(BB*TSEQ*DD)/256, 256>>>(p_sha);
    k_final<<<dim3(NTILE, HDIM/64, BB), 256>>>(out);
}